// round 13
// baseline (speedup 1.0000x reference)
#include <cuda_runtime.h>
#include <math.h>

#define Bn 64
#define Tn 512
#define En 768
#define Cn 20
#define FULL 0xffffffffu

// scratch (no allocations allowed)
__device__ float g_em[Bn * Tn * Cn];   // emissions [B][T][C]
__device__ float g_norm[Bn];
__device__ float g_score[Bn];

__device__ __forceinline__ float neg_inf() { return __int_as_float(0xff800000); }

// packed f32x2 helpers (sm_100+)
#define PACKF2(out, lo, hi) \
    asm("mov.b64 %0, {%1, %2};" : "=l"(out) : "r"(__float_as_uint(lo)), "r"(__float_as_uint(hi)))
#define UNPACKF2(lo, hi, in) \
    do { unsigned _ulo, _uhi; \
         asm("mov.b64 {%0, %1}, %2;" : "=r"(_ulo), "=r"(_uhi) : "l"(in)); \
         lo = __uint_as_float(_ulo); hi = __uint_as_float(_uhi); } while (0)
#define FMA2(d, a, b) \
    asm("fma.rn.f32x2 %0, %1, %2, %0;" : "+l"(d) : "l"(a), "l"(b))

// ---------------------------------------------------------------------------
// Kernel 1: emissions = hidden @ fc_w^T + fc_b
// warp per ROW-QUAD; FFMA2 with CONFLICT-FREE lane-major packed weight layout:
// G[cp][k][half][lane] (ulonglong2) = packed class-pairs for e=128k+4*lane+2*half+{0,1}
// Each LDS.128 is 16B/lane contiguous across the warp -> conflict degree 1.
// ---------------------------------------------------------------------------
extern "C" __global__ void __launch_bounds__(192, 2)
k_emissions(const float* __restrict__ hidden,
            const float* __restrict__ fc_w,
            const float* __restrict__ fc_b) {
    extern __shared__ float sm[];          // (Cn/2)*En float2 weights + Cn bias
    float2* wsh2 = (float2*)sm;
    float*  bsh  = sm + Cn * En;
    // fill lane-major layout: float2 entry i
    //   cp = i/768; r = i%768; k = r/128; r2 = r%128; half = r2/64; m = r2%64;
    //   l = m>>1; sub = m&1; e = 128k + 4l + 2*half + sub
    for (int i = threadIdx.x; i < (Cn / 2) * En; i += blockDim.x) {
        int cp = i / En;
        int r  = i - cp * En;
        int k  = r >> 7;
        int r2 = r & 127;
        int half = r2 >> 6;
        int m  = r2 & 63;
        int l  = m >> 1;
        int sub = m & 1;
        int e  = 128 * k + 4 * l + 2 * half + sub;
        wsh2[i] = make_float2(fc_w[(2 * cp) * En + e], fc_w[(2 * cp + 1) * En + e]);
    }
    if (threadIdx.x < Cn) bsh[threadIdx.x] = fc_b[threadIdx.x];
    __syncthreads();

    const int lane  = threadIdx.x & 31;
    const int warp  = threadIdx.x >> 5;
    const int nwarp = (blockDim.x / 32) * gridDim.x;
    const ulonglong2* wp2 = (const ulonglong2*)sm;  // 2 packed pairs per 16B load
    const int nquads = Bn * Tn / 4;                 // 8192

    for (int quad = blockIdx.x * (blockDim.x / 32) + warp; quad < nquads; quad += nwarp) {
        const float4* h0 = (const float4*)(hidden + (size_t)(4 * quad) * En);
        const float4* h1 = h0 + En / 4;
        const float4* h2 = h1 + En / 4;
        const float4* h3 = h2 + En / 4;

        unsigned long long A0[Cn / 2], A1[Cn / 2], A2[Cn / 2], A3[Cn / 2];
#pragma unroll
        for (int cp = 0; cp < Cn / 2; cp++) { A0[cp] = 0ull; A1[cp] = 0ull; A2[cp] = 0ull; A3[cp] = 0ull; }

#pragma unroll 1
        for (int k = 0; k < En / 128; k++) {        // 6 chunks, NOT unrolled
            float4 x0 = h0[lane + 32 * k];
            float4 x1 = h1[lane + 32 * k];
            float4 x2 = h2[lane + 32 * k];
            float4 x3 = h3[lane + 32 * k];
            unsigned long long x0x, x0y, x0z, x0w, x1x, x1y, x1z, x1w;
            unsigned long long x2x, x2y, x2z, x2w, x3x, x3y, x3z, x3w;
            PACKF2(x0x, x0.x, x0.x); PACKF2(x0y, x0.y, x0.y);
            PACKF2(x0z, x0.z, x0.z); PACKF2(x0w, x0.w, x0.w);
            PACKF2(x1x, x1.x, x1.x); PACKF2(x1y, x1.y, x1.y);
            PACKF2(x1z, x1.z, x1.z); PACKF2(x1w, x1.w, x1.w);
            PACKF2(x2x, x2.x, x2.x); PACKF2(x2y, x2.y, x2.y);
            PACKF2(x2z, x2.z, x2.z); PACKF2(x2w, x2.w, x2.w);
            PACKF2(x3x, x3.x, x3.x); PACKF2(x3y, x3.y, x3.y);
            PACKF2(x3z, x3.z, x3.z); PACKF2(x3w, x3.w, x3.w);
#pragma unroll
            for (int cp = 0; cp < Cn / 2; cp++) {
                // conflict-free: lane-contiguous 16B loads
                ulonglong2 wA = wp2[(cp * 12 + 2 * k)     * 32 + lane]; // e = 4l+{0,1}
                ulonglong2 wB = wp2[(cp * 12 + 2 * k + 1) * 32 + lane]; // e = 4l+{2,3}
                FMA2(A0[cp], x0x, wA.x); FMA2(A0[cp], x0y, wA.y);
                FMA2(A0[cp], x0z, wB.x); FMA2(A0[cp], x0w, wB.y);
                FMA2(A1[cp], x1x, wA.x); FMA2(A1[cp], x1y, wA.y);
                FMA2(A1[cp], x1z, wB.x); FMA2(A1[cp], x1w, wB.y);
                FMA2(A2[cp], x2x, wA.x); FMA2(A2[cp], x2y, wA.y);
                FMA2(A2[cp], x2z, wB.x); FMA2(A2[cp], x2w, wB.y);
                FMA2(A3[cp], x3x, wA.x); FMA2(A3[cp], x3y, wA.y);
                FMA2(A3[cp], x3z, wB.x); FMA2(A3[cp], x3w, wB.y);
            }
        }

        // unpack then butterfly-reduce 80 scalars across lanes
        float a0[Cn], a1[Cn], a2[Cn], a3[Cn];
#pragma unroll
        for (int cp = 0; cp < Cn / 2; cp++) {
            UNPACKF2(a0[2 * cp], a0[2 * cp + 1], A0[cp]);
            UNPACKF2(a1[2 * cp], a1[2 * cp + 1], A1[cp]);
            UNPACKF2(a2[2 * cp], a2[2 * cp + 1], A2[cp]);
            UNPACKF2(a3[2 * cp], a3[2 * cp + 1], A3[cp]);
        }
#pragma unroll
        for (int c = 0; c < Cn; c++) {
#pragma unroll
            for (int o = 16; o; o >>= 1) {
                a0[c] += __shfl_xor_sync(FULL, a0[c], o);
                a1[c] += __shfl_xor_sync(FULL, a1[c], o);
                a2[c] += __shfl_xor_sync(FULL, a2[c], o);
                a3[c] += __shfl_xor_sync(FULL, a3[c], o);
            }
        }
        if (lane < 4) {
            const float* src = (lane == 0) ? a0 : (lane == 1) ? a1 : (lane == 2) ? a2 : a3;
            float4* o4 = (float4*)(g_em + (size_t)(4 * quad + lane) * Cn);
            o4[0] = make_float4(src[0]+bsh[0],   src[1]+bsh[1],   src[2]+bsh[2],   src[3]+bsh[3]);
            o4[1] = make_float4(src[4]+bsh[4],   src[5]+bsh[5],   src[6]+bsh[6],   src[7]+bsh[7]);
            o4[2] = make_float4(src[8]+bsh[8],   src[9]+bsh[9],   src[10]+bsh[10], src[11]+bsh[11]);
            o4[3] = make_float4(src[12]+bsh[12], src[13]+bsh[13], src[14]+bsh[14], src[15]+bsh[15]);
            o4[4] = make_float4(src[16]+bsh[16], src[17]+bsh[17], src[18]+bsh[18], src[19]+bsh[19]);
        }
    }
}

// ---------------------------------------------------------------------------
// Kernel 2: blocks 0..63  -> numerator + scaled forward (warp 0)
//           blocks 64..127-> two-pass viterbi + pointer-doubled backtrace
// ---------------------------------------------------------------------------
#define SM_EM    (Tn * Cn * 4)                 // 40960  emissions -> state trajectory
#define SM_MSK   (Tn * 4)                      // 2048   mask -> path buffer
#define SM_HIST  (Tn * Cn)                     // 10240  u8 backpointers (1-step)
#define SM_HIST2 (Tn * Cn)                     // 10240  u8 backpointers (2-step)
#define SM2_SIZE (SM_EM + SM_MSK + SM_HIST + SM_HIST2 + 16)

extern "C" __global__ void __launch_bounds__(128)
k_crf(const int* __restrict__ amask,
      const int* __restrict__ labels,
      const float* __restrict__ start_t,
      const float* __restrict__ end_t,
      const float* __restrict__ trans,
      float* __restrict__ dout) {
    extern __shared__ char smraw[];
    float*         em_sh = (float*)smraw;
    int*           msk   = (int*)(smraw + SM_EM);
    unsigned char* hist8 = (unsigned char*)(smraw + SM_EM + SM_MSK);
    unsigned char* hist2 = (unsigned char*)(smraw + SM_EM + SM_MSK + SM_HIST);
    int*           misc  = (int*)(smraw + SM_EM + SM_MSK + SM_HIST + SM_HIST2);

    const int tid  = threadIdx.x;
    const bool isfwd = (blockIdx.x < Bn);
    const int b = isfwd ? blockIdx.x : blockIdx.x - Bn;

    // stage emissions + mask for this batch (all 4 warps)
    {
        const float4* src = (const float4*)(g_em + (size_t)b * Tn * Cn);
        float4* dst = (float4*)em_sh;
#pragma unroll 4
        for (int i = tid; i < Tn * Cn / 4; i += 128) dst[i] = src[i];
        for (int i = tid; i < Tn; i += 128) msk[i] = amask[b * Tn + i];
    }
    __syncthreads();

    const int lane = tid & 31;
    const bool act = lane < Cn;
    const int jj = act ? lane : 0;

    if (isfwd) {
        if (tid >= 32) return;
        // ---- numerator: gold path score (reads em_sh before it is overwritten) ----
        float ns = 0.f; int msum = 0;
        for (int t = lane; t < Tn; t += 32) {
            int tg = labels[b * Tn + t];
            msum += msk[t];
            if (t == 0) {
                ns += start_t[tg] + em_sh[tg];
            } else if (msk[t]) {
                int tp = labels[b * Tn + t - 1];
                ns += trans[tp * Cn + tg] + em_sh[t * Cn + tg];
            }
        }
        for (int o = 16; o; o >>= 1) {
            ns   += __shfl_xor_sync(FULL, ns, o);
            msum += __shfl_xor_sync(FULL, msum, o);
        }
        if (lane == 0) {
            int se = msum - 1;
            g_score[b] = ns + end_t[labels[b * Tn + se]];
        }

        // ---- denominator: scaled linear-domain forward, smem state exchange ----
        float Mc[Cn];
#pragma unroll
        for (int i = 0; i < Cn; i++) Mc[i] = act ? expf(trans[i * Cn + jj]) : 0.f;

        float p = act ? expf(start_t[jj] + em_sh[jj]) : 0.f;
        if (act) em_sh[jj] = p;                      // p_0 over consumed slot 0
        __syncwarp();

        float logZ = 0.f;
        float emc = em_sh[Cn + jj];
        int   mkc = msk[1];

        for (int t = 1; t < Tn; t++) {
            float emn = em_sh[(t + 1) * Cn + jj];    // slot t+1 pristine; t=511 overruns into msk: unused
            int   mkn = msk[t + 1];
            float Ev = __expf(emc);
            const float4* pv = (const float4*)(em_sh + (t - 1) * Cn);  // p_{t-1}, broadcast
            float4 P0 = pv[0], P1 = pv[1], P2 = pv[2], P3 = pv[3], P4 = pv[4];
            float q0, q1, q2, q3;
            q0 = P0.x * Mc[0];             q1 = P0.y * Mc[1];
            q2 = P0.z * Mc[2];             q3 = P0.w * Mc[3];
            q0 = fmaf(P1.x, Mc[4],  q0);   q1 = fmaf(P1.y, Mc[5],  q1);
            q2 = fmaf(P1.z, Mc[6],  q2);   q3 = fmaf(P1.w, Mc[7],  q3);
            q0 = fmaf(P2.x, Mc[8],  q0);   q1 = fmaf(P2.y, Mc[9],  q1);
            q2 = fmaf(P2.z, Mc[10], q2);   q3 = fmaf(P2.w, Mc[11], q3);
            q0 = fmaf(P3.x, Mc[12], q0);   q1 = fmaf(P3.y, Mc[13], q1);
            q2 = fmaf(P3.z, Mc[14], q2);   q3 = fmaf(P3.w, Mc[15], q3);
            q0 = fmaf(P4.x, Mc[16], q0);   q1 = fmaf(P4.y, Mc[17], q1);
            q2 = fmaf(P4.z, Mc[18], q2);   q3 = fmaf(P4.w, Mc[19], q3);
            float r = ((q0 + q1) + (q2 + q3)) * Ev;
            p = act ? ((mkc > 0) ? r : p) : 0.f;
            if ((t & 15) == 0) {                     // renormalize every 16 steps
                float s = p;
                for (int o = 16; o; o >>= 1) s += __shfl_xor_sync(FULL, s, o);
                p *= __fdividef(1.f, s);
                logZ += __logf(s);
            }
            if (act) em_sh[t * Cn + jj] = p;         // publish p_t over consumed slot t
            __syncwarp();
            emc = emn; mkc = mkn;
        }
        float fin = act ? p * __expf(end_t[jj]) : 0.f;
        for (int o = 16; o; o >>= 1) fin += __shfl_xor_sync(FULL, fin, o);
        if (lane == 0) g_norm[b] = logZ + __logf(fin);
        return;
    }

    // ======================= viterbi block =======================
    if (tid < 32) {
        // ---- pass 1: value recurrence (warp 0); a_t published over em_sh[t]
        float Tc[Cn];
#pragma unroll
        for (int i = 0; i < Cn; i++) Tc[i] = act ? trans[i * Cn + jj] : 0.f;

        float a = act ? (start_t[jj] + em_sh[jj]) : 0.f;
        if (act) em_sh[jj] = a;                      // a_0 over slot 0
        __syncwarp();

        float emc = em_sh[Cn + jj];
        int   mkc = msk[1];

        for (int t = 1; t < Tn; t++) {
            float emn = em_sh[(t + 1) * Cn + jj];    // slot t+1 pristine
            int   mkn = msk[t + 1];

            const float4* av = (const float4*)(em_sh + (t - 1) * Cn);  // a_{t-1}, broadcast
            float4 A0 = av[0], A1 = av[1], A2 = av[2], A3 = av[3], A4 = av[4];
            float v0  = A0.x + Tc[0],  v1  = A0.y + Tc[1];
            float v2  = A0.z + Tc[2],  v3  = A0.w + Tc[3];
            float v4  = A1.x + Tc[4],  v5  = A1.y + Tc[5];
            float v6  = A1.z + Tc[6],  v7  = A1.w + Tc[7];
            float v8  = A2.x + Tc[8],  v9  = A2.y + Tc[9];
            float v10 = A2.z + Tc[10], v11 = A2.w + Tc[11];
            float v12 = A3.x + Tc[12], v13 = A3.y + Tc[13];
            float v14 = A3.z + Tc[14], v15 = A3.w + Tc[15];
            float v16 = A4.x + Tc[16], v17 = A4.y + Tc[17];
            float v18 = A4.z + Tc[18], v19 = A4.w + Tc[19];

            float m0 = fmaxf(v0,  v1);
            float m1 = fmaxf(v2,  v3);
            float m2 = fmaxf(v4,  v5);
            float m3 = fmaxf(v6,  v7);
            float m4 = fmaxf(v8,  v9);
            float m5 = fmaxf(v10, v11);
            float m6 = fmaxf(v12, v13);
            float m7 = fmaxf(v14, v15);
            float m8 = fmaxf(v16, v17);
            float m9 = fmaxf(v18, v19);
            float best = fmaxf(fmaxf(fmaxf(fmaxf(m0, m1), fmaxf(m2, m3)),
                                     fmaxf(fmaxf(m4, m5), fmaxf(m6, m7))),
                               fmaxf(m8, m9));

            float na = best + emc;
            a = (mkc > 0) ? na : a;
            if (act) em_sh[t * Cn + jj] = a;         // publish post-mask a_t
            __syncwarp();
            emc = emn; mkc = mkn;
        }

        // final argmax over states (first max on ties)
        float fv = act ? a + end_t[jj] : neg_inf();
        int fi = lane;
        for (int o = 16; o; o >>= 1) {
            float ov = __shfl_xor_sync(FULL, fv, o);
            int   oi = __shfl_xor_sync(FULL, fi, o);
            bool tk = (ov > fv) || (ov == fv && oi < fi);
            fv = tk ? ov : fv;
            fi = tk ? oi : fi;
        }
        if (lane == 0) misc[0] = fi;
    }
    __syncthreads();

    // ---- pass 2: backpointers in parallel from stored a trajectory ----
    if (tid < 120) {
        const int j = tid % Cn;          // my target state
        const int g = tid / Cn;          // 0..5
        float Tj[Cn];
#pragma unroll
        for (int i = 0; i < Cn; i++) Tj[i] = trans[i * Cn + j];

        for (int t = 1 + g; t < Tn; t += 6) {
            const float4* ap = (const float4*)(em_sh + (t - 1) * Cn);
            float4 A0 = ap[0], A1 = ap[1], A2 = ap[2], A3 = ap[3], A4 = ap[4];
            float v[Cn];
            v[0] = A0.x + Tj[0];  v[1] = A0.y + Tj[1];  v[2] = A0.z + Tj[2];  v[3] = A0.w + Tj[3];
            v[4] = A1.x + Tj[4];  v[5] = A1.y + Tj[5];  v[6] = A1.z + Tj[6];  v[7] = A1.w + Tj[7];
            v[8] = A2.x + Tj[8];  v[9] = A2.y + Tj[9];  v[10] = A2.z + Tj[10]; v[11] = A2.w + Tj[11];
            v[12] = A3.x + Tj[12]; v[13] = A3.y + Tj[13]; v[14] = A3.z + Tj[14]; v[15] = A3.w + Tj[15];
            v[16] = A4.x + Tj[16]; v[17] = A4.y + Tj[17]; v[18] = A4.z + Tj[18]; v[19] = A4.w + Tj[19];

            float m0 = fmaxf(v[0],  v[1]);
            float m1 = fmaxf(v[2],  v[3]);
            float m2 = fmaxf(v[4],  v[5]);
            float m3 = fmaxf(v[6],  v[7]);
            float m4 = fmaxf(v[8],  v[9]);
            float m5 = fmaxf(v[10], v[11]);
            float m6 = fmaxf(v[12], v[13]);
            float m7 = fmaxf(v[14], v[15]);
            float m8 = fmaxf(v[16], v[17]);
            float m9 = fmaxf(v[18], v[19]);
            float best = fmaxf(fmaxf(fmaxf(fmaxf(m0, m1), fmaxf(m2, m3)),
                                     fmaxf(fmaxf(m4, m5), fmaxf(m6, m7))),
                               fmaxf(m8, m9));
            unsigned eqm = 0;
#pragma unroll
            for (int i = 0; i < Cn; i++) eqm |= (v[i] == best) ? (1u << i) : 0u;
            hist8[(t - 1) * Cn + j] = (unsigned char)(__ffs(eqm) - 1);
        }
    }
    __syncthreads();

    // ---- build 2-step backpointers (pointer doubling), fully parallel ----
    for (int i = tid; i < (Tn - 2) * Cn; i += 128) {
        int t = i / Cn, j = i - t * Cn;
        hist2[i] = hist8[t * Cn + hist8[(t + 1) * Cn + j]];
    }
    __syncthreads();

    // ---- backtrace: two concurrent 255-hop chains (lanes 0 and 1) ----
    float* pathf = (float*)msk;            // mask no longer needed
    if (tid < 2) {
        int fi = misc[0];
        int sl = hist8[(Tn - 2) * Cn + fi];    // state at Tn-2
        if (tid == 0) {
            pathf[Tn - 1] = (float)(fi + 1);
            int s = fi;
            for (int t = Tn - 3; t >= 1; t -= 2) {   // odd times 509..1
                s = hist2[t * Cn + s];
                pathf[t] = (float)(s + 1);
            }
        } else {
            pathf[Tn - 2] = (float)(sl + 1);
            int s = sl;
            for (int t = Tn - 4; t >= 0; t -= 2) {   // even times 508..0
                s = hist2[t * Cn + s];
                pathf[t] = (float)(s + 1);
            }
        }
    }
    __syncthreads();
    float* od = dout + 1 + b * Tn;
#pragma unroll
    for (int i = 0; i < Tn / 128; i++) od[tid + 128 * i] = pathf[tid + 128 * i];
}

// ---------------------------------------------------------------------------
// Kernel 3: loss = mean(norm - score)   (one warp)
// ---------------------------------------------------------------------------
extern "C" __global__ void k_loss(float* __restrict__ dout) {
    int i = threadIdx.x;                          // 32 threads
    float v = g_norm[i] - g_score[i];
    v += g_norm[i + 32] - g_score[i + 32];
    for (int o = 16; o; o >>= 1) v += __shfl_xor_sync(FULL, v, o);
    if (i == 0) dout[0] = v / (float)Bn;
}

// ---------------------------------------------------------------------------
extern "C" void kernel_launch(void* const* d_in, const int* in_sizes, int n_in,
                              void* d_out, int out_size) {
    const float* hidden = (const float*)d_in[0];
    const int*   amask  = (const int*)d_in[1];
    const int*   labels = (const int*)d_in[2];
    const float* fc_w   = (const float*)d_in[3];
    const float* fc_b   = (const float*)d_in[4];
    const float* st     = (const float*)d_in[5];
    const float* en     = (const float*)d_in[6];
    const float* tr     = (const float*)d_in[7];
    float* dout = (float*)d_out;

    const int smem1 = (Cn * En + Cn) * 4;
    (void)cudaFuncSetAttribute((const void*)k_emissions,
                               cudaFuncAttributeMaxDynamicSharedMemorySize, smem1);
    (void)cudaFuncSetAttribute((const void*)k_crf,
                               cudaFuncAttributeMaxDynamicSharedMemorySize, SM2_SIZE);

    k_emissions<<<296, 192, smem1>>>(hidden, fc_w, fc_b);   // 2 blocks/SM, grid-stride quads
    k_crf<<<2 * Bn, 128, SM2_SIZE>>>(amask, labels, st, en, tr, dout);
    k_loss<<<1, 32>>>(dout);
}

// round 14
// speedup vs baseline: 1.6139x; 1.6139x over previous
#include <cuda_runtime.h>
#include <math.h>

#define Bn 64
#define Tn 512
#define En 768
#define Cn 20
#define FULL 0xffffffffu

// scratch (no allocations allowed)
__device__ float g_em[Bn * Tn * Cn];   // emissions [B][T][C]
__device__ float g_norm[Bn];
__device__ float g_score[Bn];

__device__ __forceinline__ float neg_inf() { return __int_as_float(0xff800000); }

// ---------------------------------------------------------------------------
// Kernel 1: emissions = hidden @ fc_w^T + fc_b    (R9 mainloop, cheap tail)
// warp per ROW-QUAD, scalar FFMA, k-loop NOT unrolled, (256,2)
// Reduction: redistributed tree (same add tree as butterfly, no redundancy)
// ---------------------------------------------------------------------------
extern "C" __global__ void __launch_bounds__(256, 2)
k_emissions(const float* __restrict__ hidden,
            const float* __restrict__ fc_w,
            const float* __restrict__ fc_b) {
    extern __shared__ float sm[];          // Cn*En weights + Cn bias
    float* wsh = sm;
    float* bsh = sm + Cn * En;
    for (int i = threadIdx.x; i < Cn * En; i += blockDim.x) wsh[i] = fc_w[i];
    if (threadIdx.x < Cn) bsh[threadIdx.x] = fc_b[threadIdx.x];
    __syncthreads();

    const int lane  = threadIdx.x & 31;
    const int warp  = threadIdx.x >> 5;
    const float4* w4 = (const float4*)wsh;

    const int quad = blockIdx.x * (blockDim.x >> 5) + warp;   // 1024*8 = 8192 quads
    const float4* h0 = (const float4*)(hidden + (size_t)(4 * quad) * En);
    const float4* h1 = h0 + En / 4;
    const float4* h2 = h1 + En / 4;
    const float4* h3 = h2 + En / 4;

    float a0[Cn], a1[Cn], a2[Cn], a3[Cn];
#pragma unroll
    for (int c = 0; c < Cn; c++) { a0[c] = 0.f; a1[c] = 0.f; a2[c] = 0.f; a3[c] = 0.f; }

#pragma unroll 1
    for (int k = 0; k < En / 128; k++) {           // 6 chunks, NOT unrolled
        float4 x0 = h0[lane + 32 * k];
        float4 x1 = h1[lane + 32 * k];
        float4 x2 = h2[lane + 32 * k];
        float4 x3 = h3[lane + 32 * k];
#pragma unroll
        for (int c = 0; c < Cn; c++) {
            float4 w = w4[c * (En / 4) + lane + 32 * k];
            a0[c] = fmaf(x0.x, w.x, fmaf(x0.y, w.y, fmaf(x0.z, w.z, fmaf(x0.w, w.w, a0[c]))));
            a1[c] = fmaf(x1.x, w.x, fmaf(x1.y, w.y, fmaf(x1.z, w.z, fmaf(x1.w, w.w, a1[c]))));
            a2[c] = fmaf(x2.x, w.x, fmaf(x2.y, w.y, fmaf(x2.z, w.z, fmaf(x2.w, w.w, a2[c]))));
            a3[c] = fmaf(x3.x, w.x, fmaf(x3.y, w.y, fmaf(x3.z, w.z, fmaf(x3.w, w.w, a3[c]))));
        }
    }

    // ---- redistributed tree reduction (bit-identical to full butterfly) ----
    const bool lo16 = (lane & 16) == 0;
    float r0[Cn], r1[Cn];
    // stage xor16: low half keeps rows {0,1}, high half keeps rows {2,3}
#pragma unroll
    for (int c = 0; c < Cn; c++) {
        float sA = lo16 ? a2[c] : a0[c];        // ship the rows I'm dropping
        float sB = lo16 ? a3[c] : a1[c];
        float gA = __shfl_xor_sync(FULL, sA, 16);
        float gB = __shfl_xor_sync(FULL, sB, 16);
        r0[c] = (lo16 ? a0[c] : a2[c]) + gA;    // row 0 (low) / row 2 (high)
        r1[c] = (lo16 ? a1[c] : a3[c]) + gB;    // row 1 (low) / row 3 (high)
    }
    // stage xor8: (lane&8)==0 keeps r0, else keeps r1
    const bool lo8 = (lane & 8) == 0;
    float s[Cn];
#pragma unroll
    for (int c = 0; c < Cn; c++) {
        float snd = lo8 ? r1[c] : r0[c];
        float got = __shfl_xor_sync(FULL, snd, 8);
        s[c] = (lo8 ? r0[c] : r1[c]) + got;
    }
    // stages xor4, xor2, xor1: plain butterfly on 20 values
#pragma unroll
    for (int c = 0; c < Cn; c++) {
        s[c] += __shfl_xor_sync(FULL, s[c], 4);
        s[c] += __shfl_xor_sync(FULL, s[c], 2);
        s[c] += __shfl_xor_sync(FULL, s[c], 1);
    }
    // writers: lane 0 -> row0, lane 8 -> row1, lane 16 -> row2, lane 24 -> row3
    if ((lane & 7) == 0) {
        int row = lane >> 3;
        float4* o4 = (float4*)(g_em + (size_t)(4 * quad + row) * Cn);
        o4[0] = make_float4(s[0]+bsh[0],   s[1]+bsh[1],   s[2]+bsh[2],   s[3]+bsh[3]);
        o4[1] = make_float4(s[4]+bsh[4],   s[5]+bsh[5],   s[6]+bsh[6],   s[7]+bsh[7]);
        o4[2] = make_float4(s[8]+bsh[8],   s[9]+bsh[9],   s[10]+bsh[10], s[11]+bsh[11]);
        o4[3] = make_float4(s[12]+bsh[12], s[13]+bsh[13], s[14]+bsh[14], s[15]+bsh[15]);
        o4[4] = make_float4(s[16]+bsh[16], s[17]+bsh[17], s[18]+bsh[18], s[19]+bsh[19]);
    }
}

// ---------------------------------------------------------------------------
// Kernel 2: blocks 0..63  -> numerator + scaled forward (warp 0)
//           blocks 64..127-> two-pass viterbi (pass1 warp0, pass2 all threads)
// State exchange per step via smem slot overwrite + broadcast LDS
// ---------------------------------------------------------------------------
#define SM_EM    (Tn * Cn * 4)                 // 40960  emissions -> state trajectory
#define SM_MSK   (Tn * 4)                      // 2048   mask -> path buffer
#define SM_HIST  (Tn * Cn)                     // 10240  u8 backpointers
#define SM2_SIZE (SM_EM + SM_MSK + SM_HIST + 16)

extern "C" __global__ void __launch_bounds__(128)
k_crf(const int* __restrict__ amask,
      const int* __restrict__ labels,
      const float* __restrict__ start_t,
      const float* __restrict__ end_t,
      const float* __restrict__ trans,
      float* __restrict__ dout) {
    extern __shared__ char smraw[];
    float*         em_sh = (float*)smraw;
    int*           msk   = (int*)(smraw + SM_EM);
    unsigned char* hist8 = (unsigned char*)(smraw + SM_EM + SM_MSK);
    int*           misc  = (int*)(smraw + SM_EM + SM_MSK + SM_HIST);

    const int tid  = threadIdx.x;
    const bool isfwd = (blockIdx.x < Bn);
    const int b = isfwd ? blockIdx.x : blockIdx.x - Bn;

    // stage emissions + mask for this batch (all 4 warps)
    {
        const float4* src = (const float4*)(g_em + (size_t)b * Tn * Cn);
        float4* dst = (float4*)em_sh;
#pragma unroll 4
        for (int i = tid; i < Tn * Cn / 4; i += 128) dst[i] = src[i];
        for (int i = tid; i < Tn; i += 128) msk[i] = amask[b * Tn + i];
    }
    __syncthreads();

    const int lane = tid & 31;
    const bool act = lane < Cn;
    const int jj = act ? lane : 0;

    if (isfwd) {
        if (tid >= 32) return;
        // ---- numerator: gold path score (reads em_sh before it is overwritten) ----
        float ns = 0.f; int msum = 0;
        for (int t = lane; t < Tn; t += 32) {
            int tg = labels[b * Tn + t];
            msum += msk[t];
            if (t == 0) {
                ns += start_t[tg] + em_sh[tg];
            } else if (msk[t]) {
                int tp = labels[b * Tn + t - 1];
                ns += trans[tp * Cn + tg] + em_sh[t * Cn + tg];
            }
        }
        for (int o = 16; o; o >>= 1) {
            ns   += __shfl_xor_sync(FULL, ns, o);
            msum += __shfl_xor_sync(FULL, msum, o);
        }
        if (lane == 0) {
            int se = msum - 1;
            g_score[b] = ns + end_t[labels[b * Tn + se]];
        }

        // ---- denominator: scaled linear-domain forward, smem state exchange ----
        float Mc[Cn];
#pragma unroll
        for (int i = 0; i < Cn; i++) Mc[i] = act ? expf(trans[i * Cn + jj]) : 0.f;

        float p = act ? expf(start_t[jj] + em_sh[jj]) : 0.f;
        if (act) em_sh[jj] = p;                      // p_0 over consumed slot 0
        __syncwarp();

        float logZ = 0.f;
        float emc = em_sh[Cn + jj];
        int   mkc = msk[1];

        for (int t = 1; t < Tn; t++) {
            float emn = em_sh[(t + 1) * Cn + jj];    // slot t+1 pristine; t=511 overruns into msk: unused
            int   mkn = msk[t + 1];
            float Ev = __expf(emc);
            const float4* pv = (const float4*)(em_sh + (t - 1) * Cn);  // p_{t-1}, broadcast
            float4 P0 = pv[0], P1 = pv[1], P2 = pv[2], P3 = pv[3], P4 = pv[4];
            float q0, q1, q2, q3;
            q0 = P0.x * Mc[0];             q1 = P0.y * Mc[1];
            q2 = P0.z * Mc[2];             q3 = P0.w * Mc[3];
            q0 = fmaf(P1.x, Mc[4],  q0);   q1 = fmaf(P1.y, Mc[5],  q1);
            q2 = fmaf(P1.z, Mc[6],  q2);   q3 = fmaf(P1.w, Mc[7],  q3);
            q0 = fmaf(P2.x, Mc[8],  q0);   q1 = fmaf(P2.y, Mc[9],  q1);
            q2 = fmaf(P2.z, Mc[10], q2);   q3 = fmaf(P2.w, Mc[11], q3);
            q0 = fmaf(P3.x, Mc[12], q0);   q1 = fmaf(P3.y, Mc[13], q1);
            q2 = fmaf(P3.z, Mc[14], q2);   q3 = fmaf(P3.w, Mc[15], q3);
            q0 = fmaf(P4.x, Mc[16], q0);   q1 = fmaf(P4.y, Mc[17], q1);
            q2 = fmaf(P4.z, Mc[18], q2);   q3 = fmaf(P4.w, Mc[19], q3);
            float r = ((q0 + q1) + (q2 + q3)) * Ev;
            p = act ? ((mkc > 0) ? r : p) : 0.f;
            if ((t & 15) == 0) {                     // renormalize every 16 steps
                float sR = p;
                for (int o = 16; o; o >>= 1) sR += __shfl_xor_sync(FULL, sR, o);
                p *= __fdividef(1.f, sR);
                logZ += __logf(sR);
            }
            if (act) em_sh[t * Cn + jj] = p;         // publish p_t over consumed slot t
            __syncwarp();
            emc = emn; mkc = mkn;
        }
        float fin = act ? p * __expf(end_t[jj]) : 0.f;
        for (int o = 16; o; o >>= 1) fin += __shfl_xor_sync(FULL, fin, o);
        if (lane == 0) g_norm[b] = logZ + __logf(fin);
        return;
    }

    // ======================= viterbi block =======================
    if (tid < 32) {
        // ---- pass 1: value recurrence (warp 0); a_t published over em_sh[t]
        float Tc[Cn];
#pragma unroll
        for (int i = 0; i < Cn; i++) Tc[i] = act ? trans[i * Cn + jj] : 0.f;

        float a = act ? (start_t[jj] + em_sh[jj]) : 0.f;
        if (act) em_sh[jj] = a;                      // a_0 over slot 0
        __syncwarp();

        float emc = em_sh[Cn + jj];
        int   mkc = msk[1];

        for (int t = 1; t < Tn; t++) {
            float emn = em_sh[(t + 1) * Cn + jj];    // slot t+1 pristine
            int   mkn = msk[t + 1];

            const float4* av = (const float4*)(em_sh + (t - 1) * Cn);  // a_{t-1}, broadcast
            float4 A0 = av[0], A1 = av[1], A2 = av[2], A3 = av[3], A4 = av[4];
            float v0  = A0.x + Tc[0],  v1  = A0.y + Tc[1];
            float v2  = A0.z + Tc[2],  v3  = A0.w + Tc[3];
            float v4  = A1.x + Tc[4],  v5  = A1.y + Tc[5];
            float v6  = A1.z + Tc[6],  v7  = A1.w + Tc[7];
            float v8  = A2.x + Tc[8],  v9  = A2.y + Tc[9];
            float v10 = A2.z + Tc[10], v11 = A2.w + Tc[11];
            float v12 = A3.x + Tc[12], v13 = A3.y + Tc[13];
            float v14 = A3.z + Tc[14], v15 = A3.w + Tc[15];
            float v16 = A4.x + Tc[16], v17 = A4.y + Tc[17];
            float v18 = A4.z + Tc[18], v19 = A4.w + Tc[19];

            float m0 = fmaxf(v0,  v1);
            float m1 = fmaxf(v2,  v3);
            float m2 = fmaxf(v4,  v5);
            float m3 = fmaxf(v6,  v7);
            float m4 = fmaxf(v8,  v9);
            float m5 = fmaxf(v10, v11);
            float m6 = fmaxf(v12, v13);
            float m7 = fmaxf(v14, v15);
            float m8 = fmaxf(v16, v17);
            float m9 = fmaxf(v18, v19);
            float best = fmaxf(fmaxf(fmaxf(fmaxf(m0, m1), fmaxf(m2, m3)),
                                     fmaxf(fmaxf(m4, m5), fmaxf(m6, m7))),
                               fmaxf(m8, m9));

            float na = best + emc;
            a = (mkc > 0) ? na : a;
            if (act) em_sh[t * Cn + jj] = a;         // publish post-mask a_t
            __syncwarp();
            emc = emn; mkc = mkn;
        }

        // final argmax over states (first max on ties)
        float fv = act ? a + end_t[jj] : neg_inf();
        int fi = lane;
        for (int o = 16; o; o >>= 1) {
            float ov = __shfl_xor_sync(FULL, fv, o);
            int   oi = __shfl_xor_sync(FULL, fi, o);
            bool tk = (ov > fv) || (ov == fv && oi < fi);
            fv = tk ? ov : fv;
            fi = tk ? oi : fi;
        }
        if (lane == 0) misc[0] = fi;
    }
    __syncthreads();

    // ---- pass 2: backpointers in parallel from stored a trajectory ----
    if (tid < 120) {
        const int j = tid % Cn;          // my target state
        const int g = tid / Cn;          // 0..5
        float Tj[Cn];
#pragma unroll
        for (int i = 0; i < Cn; i++) Tj[i] = trans[i * Cn + j];

        for (int t = 1 + g; t < Tn; t += 6) {
            const float4* ap = (const float4*)(em_sh + (t - 1) * Cn);
            float4 A0 = ap[0], A1 = ap[1], A2 = ap[2], A3 = ap[3], A4 = ap[4];
            float v[Cn];
            v[0] = A0.x + Tj[0];  v[1] = A0.y + Tj[1];  v[2] = A0.z + Tj[2];  v[3] = A0.w + Tj[3];
            v[4] = A1.x + Tj[4];  v[5] = A1.y + Tj[5];  v[6] = A1.z + Tj[6];  v[7] = A1.w + Tj[7];
            v[8] = A2.x + Tj[8];  v[9] = A2.y + Tj[9];  v[10] = A2.z + Tj[10]; v[11] = A2.w + Tj[11];
            v[12] = A3.x + Tj[12]; v[13] = A3.y + Tj[13]; v[14] = A3.z + Tj[14]; v[15] = A3.w + Tj[15];
            v[16] = A4.x + Tj[16]; v[17] = A4.y + Tj[17]; v[18] = A4.z + Tj[18]; v[19] = A4.w + Tj[19];

            float m0 = fmaxf(v[0],  v[1]);
            float m1 = fmaxf(v[2],  v[3]);
            float m2 = fmaxf(v[4],  v[5]);
            float m3 = fmaxf(v[6],  v[7]);
            float m4 = fmaxf(v[8],  v[9]);
            float m5 = fmaxf(v[10], v[11]);
            float m6 = fmaxf(v[12], v[13]);
            float m7 = fmaxf(v[14], v[15]);
            float m8 = fmaxf(v[16], v[17]);
            float m9 = fmaxf(v[18], v[19]);
            float best = fmaxf(fmaxf(fmaxf(fmaxf(m0, m1), fmaxf(m2, m3)),
                                     fmaxf(fmaxf(m4, m5), fmaxf(m6, m7))),
                               fmaxf(m8, m9));
            unsigned eqm = 0;
#pragma unroll
            for (int i = 0; i < Cn; i++) eqm |= (v[i] == best) ? (1u << i) : 0u;
            hist8[(t - 1) * Cn + j] = (unsigned char)(__ffs(eqm) - 1);
        }
    }
    __syncthreads();

    // ---- serial backtrace into smem, then coalesced write-out ----
    float* pathf = (float*)msk;            // mask no longer needed
    if (tid == 0) {
        int tg = misc[0];
        pathf[Tn - 1] = (float)(tg + 1);
        for (int t = Tn - 2; t >= 0; t--) {
            tg = hist8[t * Cn + tg];
            pathf[t] = (float)(tg + 1);
        }
    }
    __syncthreads();
    float* od = dout + 1 + b * Tn;
#pragma unroll
    for (int i = 0; i < Tn / 128; i++) od[tid + 128 * i] = pathf[tid + 128 * i];
}

// ---------------------------------------------------------------------------
// Kernel 3: loss = mean(norm - score)   (one warp)
// ---------------------------------------------------------------------------
extern "C" __global__ void k_loss(float* __restrict__ dout) {
    int i = threadIdx.x;                          // 32 threads
    float v = g_norm[i] - g_score[i];
    v += g_norm[i + 32] - g_score[i + 32];
    for (int o = 16; o; o >>= 1) v += __shfl_xor_sync(FULL, v, o);
    if (i == 0) dout[0] = v / (float)Bn;
}

// ---------------------------------------------------------------------------
extern "C" void kernel_launch(void* const* d_in, const int* in_sizes, int n_in,
                              void* d_out, int out_size) {
    const float* hidden = (const float*)d_in[0];
    const int*   amask  = (const int*)d_in[1];
    const int*   labels = (const int*)d_in[2];
    const float* fc_w   = (const float*)d_in[3];
    const float* fc_b   = (const float*)d_in[4];
    const float* st     = (const float*)d_in[5];
    const float* en     = (const float*)d_in[6];
    const float* tr     = (const float*)d_in[7];
    float* dout = (float*)d_out;

    const int smem1 = (Cn * En + Cn) * 4;
    (void)cudaFuncSetAttribute((const void*)k_emissions,
                               cudaFuncAttributeMaxDynamicSharedMemorySize, smem1);
    (void)cudaFuncSetAttribute((const void*)k_crf,
                               cudaFuncAttributeMaxDynamicSharedMemorySize, SM2_SIZE);

    k_emissions<<<1024, 256, smem1>>>(hidden, fc_w, fc_b);   // 8192 quads
    k_crf<<<2 * Bn, 128, SM2_SIZE>>>(amask, labels, st, en, tr, dout);
    k_loss<<<1, 32>>>(dout);
}